// round 9
// baseline (speedup 1.0000x reference)
#include <cuda_runtime.h>
#include <cuda_bf16.h>

// Problem constants
#define B 8
#define N 2048
#define D 1024
#define G 8
#define CAP 320
#define NTOK (B*N)              // 16384
#define SLAB (G*CAP)            // 2560 floats per token
#define TB 16                   // tokens per gate block
#define NGATE (NTOK/TB)         // 1024 gate blocks
#define NZERO 1024              // zero blocks
#define TOTAL_F4 (NTOK*SLAB/4)  // 10485760
#define ZBLK (TOTAL_F4/NZERO)   // 10240 float4 per zero block
#define ZPT (ZBLK/256)          // 40 float4 per zero thread

// Scratch: one packed record per token: {pack bits, g1n, g2n, 0}
__device__ float4 g_rec[NTOK];

// ---------------------------------------------------------------------------
// K1: block-role-specialized fused kernel, mod-2 interleave (1:1 gate:zero).
//   even bid -> gate block (1024, TB=16); odd bid -> zero block (1024).
// No fences, no atomics: ordering vs the scatter comes from the kernel
// boundary (the R7/R8 lesson).
// ---------------------------------------------------------------------------
__global__ __launch_bounds__(256) void k_fused(const float* __restrict__ x,
                                               const float* __restrict__ w,
                                               float* __restrict__ out) {
    int bid = blockIdx.x;
    int tid = threadIdx.x;
    const unsigned FULL = 0xffffffffu;

    if (bid & 1) {
        // ---------------- zero role ----------------
        int zid = bid >> 1;                           // 0..1023
        float4* zbase = (float4*)out + (size_t)zid * ZBLK + tid;
        const float4 ZV = make_float4(0.f, 0.f, 0.f, 0.f);
#pragma unroll
        for (int j = 0; j < ZPT; j++)
            zbase[j * 256] = ZV;
        return;
    }

    // ---------------- gate role ----------------
    __shared__ float part[G * 8 * TB];   // 4 KB

    int warp = tid >> 5, lane = tid & 31;
    int k0 = warp * 128 + lane * 4;

    // W coefficients for owned k's -> registers (w is [D, G] row-major)
    float4 wv0 = *(const float4*)(w + k0 * G + 0);
    float4 wv1 = *(const float4*)(w + k0 * G + 4);
    float4 wv2 = *(const float4*)(w + k0 * G + 8);
    float4 wv3 = *(const float4*)(w + k0 * G + 12);
    float4 wv4 = *(const float4*)(w + k0 * G + 16);
    float4 wv5 = *(const float4*)(w + k0 * G + 20);
    float4 wv6 = *(const float4*)(w + k0 * G + 24);
    float4 wv7 = *(const float4*)(w + k0 * G + 28);
    float wreg[G][4];
    wreg[0][0]=wv0.x; wreg[1][0]=wv0.y; wreg[2][0]=wv0.z; wreg[3][0]=wv0.w;
    wreg[4][0]=wv1.x; wreg[5][0]=wv1.y; wreg[6][0]=wv1.z; wreg[7][0]=wv1.w;
    wreg[0][1]=wv2.x; wreg[1][1]=wv2.y; wreg[2][1]=wv2.z; wreg[3][1]=wv2.w;
    wreg[4][1]=wv3.x; wreg[5][1]=wv3.y; wreg[6][1]=wv3.z; wreg[7][1]=wv3.w;
    wreg[0][2]=wv4.x; wreg[1][2]=wv4.y; wreg[2][2]=wv4.z; wreg[3][2]=wv4.w;
    wreg[4][2]=wv5.x; wreg[5][2]=wv5.y; wreg[6][2]=wv5.z; wreg[7][2]=wv5.w;
    wreg[0][3]=wv6.x; wreg[1][3]=wv6.y; wreg[2][3]=wv6.z; wreg[3][3]=wv6.w;
    wreg[4][3]=wv7.x; wreg[5][3]=wv7.y; wreg[6][3]=wv7.z; wreg[7][3]=wv7.w;

    int tok0 = (bid >> 1) * TB;
    int bit0 = lane & 1;
    int my_e = (lane & 1) * 4 + (lane & 2) + ((lane >> 2) & 1);

#pragma unroll 4
    for (int t = 0; t < TB; t++) {
        const float4 xv = *(const float4*)(x + (size_t)(tok0 + t) * D + k0);

        float acc[G];
#pragma unroll
        for (int e = 0; e < G; e++) {
            acc[e] = fmaf(xv.x, wreg[e][0],
                     fmaf(xv.y, wreg[e][1],
                     fmaf(xv.z, wreg[e][2],
                          xv.w * wreg[e][3])));
        }

        float a0 = (bit0 ? acc[4] : acc[0]) + __shfl_xor_sync(FULL, bit0 ? acc[0] : acc[4], 1);
        float a1 = (bit0 ? acc[5] : acc[1]) + __shfl_xor_sync(FULL, bit0 ? acc[1] : acc[5], 1);
        float a2 = (bit0 ? acc[6] : acc[2]) + __shfl_xor_sync(FULL, bit0 ? acc[2] : acc[6], 1);
        float a3 = (bit0 ? acc[7] : acc[3]) + __shfl_xor_sync(FULL, bit0 ? acc[3] : acc[7], 1);
        int bit1 = (lane >> 1) & 1;
        float b0 = (bit1 ? a2 : a0) + __shfl_xor_sync(FULL, bit1 ? a0 : a2, 2);
        float b1 = (bit1 ? a3 : a1) + __shfl_xor_sync(FULL, bit1 ? a1 : a3, 2);
        int bit2 = (lane >> 2) & 1;
        float c = (bit2 ? b1 : b0) + __shfl_xor_sync(FULL, bit2 ? b0 : b1, 4);
        c += __shfl_xor_sync(FULL, c, 8);
        c += __shfl_xor_sync(FULL, c, 16);

        if (lane < 8)
            part[(my_e * 8 + warp) * TB + t] = c;
    }
    __syncthreads();

    if (tid < TB) {
        int t = tid;
        float p[G];
#pragma unroll
        for (int e = 0; e < G; e++) {
            float s = 0.f;
#pragma unroll
            for (int wq = 0; wq < 8; wq++) s += part[(e * 8 + wq) * TB + t];
            p[e] = s;
        }
        float m = p[0];
#pragma unroll
        for (int e = 1; e < G; e++) m = fmaxf(m, p[e]);
        float s = 0.f;
#pragma unroll
        for (int e = 0; e < G; e++) { p[e] = expf(p[e] - m); s += p[e]; }
        float inv = 1.f / s;
#pragma unroll
        for (int e = 0; e < G; e++) p[e] *= inv;

        int i1 = 0; float g1 = p[0];
#pragma unroll
        for (int e = 1; e < G; e++) if (p[e] > g1) { g1 = p[e]; i1 = e; }
        int i2 = 0; float g2 = -1.f;
#pragma unroll
        for (int e = 0; e < G; e++)
            if (e != i1 && p[e] > g2) { g2 = p[e]; i2 = e; }

        float g1n = g1 / (g1 + g2 + 1e-9f);
        float g2n = g2 / (g1n + g2 + 1e-9f);
        int use2 = (g2n > 0.2f) ? 1 : 0;

        int pack = i1 | (i2 << 4) | (use2 << 8);
        g_rec[tok0 + t] = make_float4(__int_as_float(pack), g1n, g2n, 0.f);
    }
}

// ---------------------------------------------------------------------------
// K2: scan + scatter. 1 block per batch, 1024 threads x 2 tokens (shortest
// serial chains, 32 warps of latency hiding). Counters packed as 2 x u64
// (16 bits per expert); warp-shuffle scans + 32-entry smem combine.
// ---------------------------------------------------------------------------
__global__ __launch_bounds__(1024) void k_scan_scatter(float* __restrict__ out) {
    __shared__ unsigned long long wlo[32], whi[32];
    __shared__ int count1[G];

    int b = blockIdx.x, tid = threadIdx.x;
    int warp = tid >> 5, lane = tid & 31;
    int base = b * N + tid * 2;
    const unsigned FULL = 0xffffffffu;

    int pk[2]; float gg1[2], gg2[2];
#pragma unroll
    for (int j = 0; j < 2; j++) {
        float4 r = g_rec[base + j];
        pk[j] = __float_as_int(r.x);
        gg1[j] = r.y; gg2[j] = r.z;
    }

    // ================= pass 1: top-1 =================
    unsigned long long lo = 0, hi = 0;
#pragma unroll
    for (int j = 0; j < 2; j++) {
        int i1 = pk[j] & 15;
        if (i1 < 4) lo += 1ULL << (i1 * 16); else hi += 1ULL << ((i1 - 4) * 16);
    }
    unsigned long long slo = lo, shi = hi;
#pragma unroll
    for (int o = 1; o < 32; o <<= 1) {
        unsigned long long t1 = __shfl_up_sync(FULL, slo, o);
        unsigned long long t2 = __shfl_up_sync(FULL, shi, o);
        if (lane >= o) { slo += t1; shi += t2; }
    }
    if (lane == 31) { wlo[warp] = slo; whi[warp] = shi; }
    __syncthreads();
    unsigned long long plo = 0, phi = 0, tlo = 0, thi = 0;
#pragma unroll
    for (int ww = 0; ww < 32; ww++) {
        unsigned long long a = wlo[ww], c = whi[ww];
        if (ww < warp) { plo += a; phi += c; }
        tlo += a; thi += c;
    }
    unsigned long long exlo = plo + slo - lo;
    unsigned long long exhi = phi + shi - hi;
#pragma unroll
    for (int e = 0; e < 4; e++) {
        count1[e]     = min((int)((tlo >> (e * 16)) & 0xFFFF), CAP);
        count1[e + 4] = min((int)((thi >> (e * 16)) & 0xFFFF), CAP);
    }
    int pos1[2];
    {
        unsigned long long rlo = exlo, rhi = exhi;
#pragma unroll
        for (int j = 0; j < 2; j++) {
            int i1 = pk[j] & 15;
            pos1[j] = (i1 < 4) ? (int)((rlo >> (i1 * 16)) & 0xFFFF)
                               : (int)((rhi >> ((i1 - 4) * 16)) & 0xFFFF);
            if (i1 < 4) rlo += 1ULL << (i1 * 16); else rhi += 1ULL << ((i1 - 4) * 16);
        }
    }
    __syncthreads();   // wlo/whi reuse

    // ================= pass 2: top-2 =================
    lo = 0; hi = 0;
#pragma unroll
    for (int j = 0; j < 2; j++) {
        if (pk[j] >> 8) {
            int i2 = (pk[j] >> 4) & 15;
            if (i2 < 4) lo += 1ULL << (i2 * 16); else hi += 1ULL << ((i2 - 4) * 16);
        }
    }
    slo = lo; shi = hi;
#pragma unroll
    for (int o = 1; o < 32; o <<= 1) {
        unsigned long long t1 = __shfl_up_sync(FULL, slo, o);
        unsigned long long t2 = __shfl_up_sync(FULL, shi, o);
        if (lane >= o) { slo += t1; shi += t2; }
    }
    if (lane == 31) { wlo[warp] = slo; whi[warp] = shi; }
    __syncthreads();
    plo = 0; phi = 0;
#pragma unroll
    for (int ww = 0; ww < 32; ww++) {
        if (ww < warp) { plo += wlo[ww]; phi += whi[ww]; }
    }
    exlo = plo + slo - lo;
    exhi = phi + shi - hi;

    unsigned long long rlo = exlo, rhi = exhi;
#pragma unroll
    for (int j = 0; j < 2; j++) {
        int t = base + j;
        int i1 = pk[j] & 15, i2 = (pk[j] >> 4) & 15, use2 = pk[j] >> 8;
        float* o = out + (size_t)t * SLAB;
        if (pos1[j] < CAP) o[i1 * CAP + pos1[j]] = gg1[j];
        if (use2) {
            int p = (i2 < 4) ? (int)((rlo >> (i2 * 16)) & 0xFFFF)
                             : (int)((rhi >> ((i2 - 4) * 16)) & 0xFFFF);
            int pos2 = count1[i2] + p;
            if (pos2 < CAP) o[i2 * CAP + pos2] = gg2[j];
            if (i2 < 4) rlo += 1ULL << (i2 * 16); else rhi += 1ULL << ((i2 - 4) * 16);
        }
    }
}

extern "C" void kernel_launch(void* const* d_in, const int* in_sizes, int n_in,
                              void* d_out, int out_size) {
    const float* x = (const float*)d_in[0];
    const float* w = (const float*)d_in[1];
    float* out = (float*)d_out;

    k_fused<<<NGATE + NZERO, 256>>>(x, w, out);
    k_scan_scatter<<<B, 1024>>>(out);
}

// round 10
// speedup vs baseline: 1.1530x; 1.1530x over previous
#include <cuda_runtime.h>
#include <cuda_bf16.h>

// Problem constants
#define B 8
#define N 2048
#define D 1024
#define G 8
#define CAP 320
#define NTOK (B*N)              // 16384
#define SLAB (G*CAP)            // 2560 floats per token
#define TB 32                   // tokens per gate block
#define NGATE (NTOK/TB)         // 512 gate blocks
#define NZERO 1024              // zero blocks
#define TOTAL_F4 (NTOK*SLAB/4)  // 10485760
#define ZBLK (TOTAL_F4/NZERO)   // 10240 float4 per zero block
#define ZPT (ZBLK/256)          // 40 float4 per zero thread

// Scratch: one packed record per token: {pack bits, g1n, g2n, 0}
__device__ float4 g_rec[NTOK];

// ---------------------------------------------------------------------------
// K1: block-role-specialized fused kernel (exact R5 structure — best measured).
//   blockIdx % 3 == 0 -> gate block (512, TB=32); else zero block (1024).
// Plain stores, no fences/atomics; ordering vs scatter = kernel boundary.
// ---------------------------------------------------------------------------
__global__ __launch_bounds__(256) void k_fused(const float* __restrict__ x,
                                               const float* __restrict__ w,
                                               float* __restrict__ out) {
    int bid = blockIdx.x;
    int mod = bid % 3;
    int tid = threadIdx.x;
    const unsigned FULL = 0xffffffffu;

    if (mod != 0) {
        // ---------------- zero role ----------------
        int zid = (bid / 3) * 2 + (mod - 1);          // 0..1023
        float4* zbase = (float4*)out + (size_t)zid * ZBLK + tid;
        const float4 ZV = make_float4(0.f, 0.f, 0.f, 0.f);
#pragma unroll
        for (int j = 0; j < ZPT; j++)
            zbase[j * 256] = ZV;
        return;
    }

    // ---------------- gate role ----------------
    __shared__ float part[G * 8 * TB];   // 8 KB

    int warp = tid >> 5, lane = tid & 31;
    int k0 = warp * 128 + lane * 4;

    // W coefficients for owned k's -> registers (w is [D, G] row-major)
    float4 wv0 = *(const float4*)(w + k0 * G + 0);
    float4 wv1 = *(const float4*)(w + k0 * G + 4);
    float4 wv2 = *(const float4*)(w + k0 * G + 8);
    float4 wv3 = *(const float4*)(w + k0 * G + 12);
    float4 wv4 = *(const float4*)(w + k0 * G + 16);
    float4 wv5 = *(const float4*)(w + k0 * G + 20);
    float4 wv6 = *(const float4*)(w + k0 * G + 24);
    float4 wv7 = *(const float4*)(w + k0 * G + 28);
    float wreg[G][4];
    wreg[0][0]=wv0.x; wreg[1][0]=wv0.y; wreg[2][0]=wv0.z; wreg[3][0]=wv0.w;
    wreg[4][0]=wv1.x; wreg[5][0]=wv1.y; wreg[6][0]=wv1.z; wreg[7][0]=wv1.w;
    wreg[0][1]=wv2.x; wreg[1][1]=wv2.y; wreg[2][1]=wv2.z; wreg[3][1]=wv2.w;
    wreg[4][1]=wv3.x; wreg[5][1]=wv3.y; wreg[6][1]=wv3.z; wreg[7][1]=wv3.w;
    wreg[0][2]=wv4.x; wreg[1][2]=wv4.y; wreg[2][2]=wv4.z; wreg[3][2]=wv4.w;
    wreg[4][2]=wv5.x; wreg[5][2]=wv5.y; wreg[6][2]=wv5.z; wreg[7][2]=wv5.w;
    wreg[0][3]=wv6.x; wreg[1][3]=wv6.y; wreg[2][3]=wv6.z; wreg[3][3]=wv6.w;
    wreg[4][3]=wv7.x; wreg[5][3]=wv7.y; wreg[6][3]=wv7.z; wreg[7][3]=wv7.w;

    int tok0 = (bid / 3) * TB;
    int bit0 = lane & 1;
    int my_e = (lane & 1) * 4 + (lane & 2) + ((lane >> 2) & 1);

#pragma unroll 4
    for (int t = 0; t < TB; t++) {
        const float4 xv = *(const float4*)(x + (size_t)(tok0 + t) * D + k0);

        float acc[G];
#pragma unroll
        for (int e = 0; e < G; e++) {
            acc[e] = fmaf(xv.x, wreg[e][0],
                     fmaf(xv.y, wreg[e][1],
                     fmaf(xv.z, wreg[e][2],
                          xv.w * wreg[e][3])));
        }

        float a0 = (bit0 ? acc[4] : acc[0]) + __shfl_xor_sync(FULL, bit0 ? acc[0] : acc[4], 1);
        float a1 = (bit0 ? acc[5] : acc[1]) + __shfl_xor_sync(FULL, bit0 ? acc[1] : acc[5], 1);
        float a2 = (bit0 ? acc[6] : acc[2]) + __shfl_xor_sync(FULL, bit0 ? acc[2] : acc[6], 1);
        float a3 = (bit0 ? acc[7] : acc[3]) + __shfl_xor_sync(FULL, bit0 ? acc[3] : acc[7], 1);
        int bit1 = (lane >> 1) & 1;
        float b0 = (bit1 ? a2 : a0) + __shfl_xor_sync(FULL, bit1 ? a0 : a2, 2);
        float b1 = (bit1 ? a3 : a1) + __shfl_xor_sync(FULL, bit1 ? a1 : a3, 2);
        int bit2 = (lane >> 2) & 1;
        float c = (bit2 ? b1 : b0) + __shfl_xor_sync(FULL, bit2 ? b0 : b1, 4);
        c += __shfl_xor_sync(FULL, c, 8);
        c += __shfl_xor_sync(FULL, c, 16);

        if (lane < 8)
            part[(my_e * 8 + warp) * TB + t] = c;
    }
    __syncthreads();

    if (tid < TB) {
        int t = tid;
        float p[G];
#pragma unroll
        for (int e = 0; e < G; e++) {
            float s = 0.f;
#pragma unroll
            for (int wq = 0; wq < 8; wq++) s += part[(e * 8 + wq) * TB + t];
            p[e] = s;
        }
        float m = p[0];
#pragma unroll
        for (int e = 1; e < G; e++) m = fmaxf(m, p[e]);
        float s = 0.f;
#pragma unroll
        for (int e = 0; e < G; e++) { p[e] = expf(p[e] - m); s += p[e]; }
        float inv = 1.f / s;
#pragma unroll
        for (int e = 0; e < G; e++) p[e] *= inv;

        int i1 = 0; float g1 = p[0];
#pragma unroll
        for (int e = 1; e < G; e++) if (p[e] > g1) { g1 = p[e]; i1 = e; }
        int i2 = 0; float g2 = -1.f;
#pragma unroll
        for (int e = 0; e < G; e++)
            if (e != i1 && p[e] > g2) { g2 = p[e]; i2 = e; }

        float g1n = g1 / (g1 + g2 + 1e-9f);
        float g2n = g2 / (g1n + g2 + 1e-9f);
        int use2 = (g2n > 0.2f) ? 1 : 0;

        int pack = i1 | (i2 << 4) | (use2 << 8);
        g_rec[tok0 + t] = make_float4(__int_as_float(pack), g1n, g2n, 0.f);
    }
}

// ---------------------------------------------------------------------------
// K2: scan + scatter (exact R6 structure — best measured: 7.4us).
// 1 block per batch, 512 threads x 4 tokens. Packed float4 record -> one
// LDG.128 per token. Counters packed as 2 x u64 (16 bits per expert);
// warp-shuffle scans + 16-entry smem combine.
// ---------------------------------------------------------------------------
__global__ __launch_bounds__(512) void k_scan_scatter(float* __restrict__ out) {
    __shared__ unsigned long long wlo[16], whi[16];
    __shared__ int count1[G];

    int b = blockIdx.x, tid = threadIdx.x;
    int warp = tid >> 5, lane = tid & 31;
    int base = b * N + tid * 4;
    const unsigned FULL = 0xffffffffu;

    int pk[4]; float gg1[4], gg2[4];
#pragma unroll
    for (int j = 0; j < 4; j++) {
        float4 r = g_rec[base + j];
        pk[j] = __float_as_int(r.x);
        gg1[j] = r.y; gg2[j] = r.z;
    }

    // ================= pass 1: top-1 =================
    unsigned long long lo = 0, hi = 0;
#pragma unroll
    for (int j = 0; j < 4; j++) {
        int i1 = pk[j] & 15;
        if (i1 < 4) lo += 1ULL << (i1 * 16); else hi += 1ULL << ((i1 - 4) * 16);
    }
    unsigned long long slo = lo, shi = hi;
#pragma unroll
    for (int o = 1; o < 32; o <<= 1) {
        unsigned long long t1 = __shfl_up_sync(FULL, slo, o);
        unsigned long long t2 = __shfl_up_sync(FULL, shi, o);
        if (lane >= o) { slo += t1; shi += t2; }
    }
    if (lane == 31) { wlo[warp] = slo; whi[warp] = shi; }
    __syncthreads();
    unsigned long long plo = 0, phi = 0, tlo = 0, thi = 0;
#pragma unroll
    for (int ww = 0; ww < 16; ww++) {
        unsigned long long a = wlo[ww], c = whi[ww];
        if (ww < warp) { plo += a; phi += c; }
        tlo += a; thi += c;
    }
    unsigned long long exlo = plo + slo - lo;
    unsigned long long exhi = phi + shi - hi;
#pragma unroll
    for (int e = 0; e < 4; e++) {
        count1[e]     = min((int)((tlo >> (e * 16)) & 0xFFFF), CAP);
        count1[e + 4] = min((int)((thi >> (e * 16)) & 0xFFFF), CAP);
    }
    int pos1[4];
    {
        unsigned long long rlo = exlo, rhi = exhi;
#pragma unroll
        for (int j = 0; j < 4; j++) {
            int i1 = pk[j] & 15;
            pos1[j] = (i1 < 4) ? (int)((rlo >> (i1 * 16)) & 0xFFFF)
                               : (int)((rhi >> ((i1 - 4) * 16)) & 0xFFFF);
            if (i1 < 4) rlo += 1ULL << (i1 * 16); else rhi += 1ULL << ((i1 - 4) * 16);
        }
    }
    __syncthreads();   // wlo/whi reuse

    // ================= pass 2: top-2 =================
    lo = 0; hi = 0;
#pragma unroll
    for (int j = 0; j < 4; j++) {
        if (pk[j] >> 8) {
            int i2 = (pk[j] >> 4) & 15;
            if (i2 < 4) lo += 1ULL << (i2 * 16); else hi += 1ULL << ((i2 - 4) * 16);
        }
    }
    slo = lo; shi = hi;
#pragma unroll
    for (int o = 1; o < 32; o <<= 1) {
        unsigned long long t1 = __shfl_up_sync(FULL, slo, o);
        unsigned long long t2 = __shfl_up_sync(FULL, shi, o);
        if (lane >= o) { slo += t1; shi += t2; }
    }
    if (lane == 31) { wlo[warp] = slo; whi[warp] = shi; }
    __syncthreads();
    plo = 0; phi = 0;
#pragma unroll
    for (int ww = 0; ww < 16; ww++) {
        if (ww < warp) { plo += wlo[ww]; phi += whi[ww]; }
    }
    exlo = plo + slo - lo;
    exhi = phi + shi - hi;

    unsigned long long rlo = exlo, rhi = exhi;
#pragma unroll
    for (int j = 0; j < 4; j++) {
        int t = base + j;
        int i1 = pk[j] & 15, i2 = (pk[j] >> 4) & 15, use2 = pk[j] >> 8;
        float* o = out + (size_t)t * SLAB;
        if (pos1[j] < CAP) o[i1 * CAP + pos1[j]] = gg1[j];
        if (use2) {
            int p = (i2 < 4) ? (int)((rlo >> (i2 * 16)) & 0xFFFF)
                             : (int)((rhi >> ((i2 - 4) * 16)) & 0xFFFF);
            int pos2 = count1[i2] + p;
            if (pos2 < CAP) o[i2 * CAP + pos2] = gg2[j];
            if (i2 < 4) rlo += 1ULL << (i2 * 16); else rhi += 1ULL << ((i2 - 4) * 16);
        }
    }
}

extern "C" void kernel_launch(void* const* d_in, const int* in_sizes, int n_in,
                              void* d_out, int out_size) {
    const float* x = (const float*)d_in[0];
    const float* w = (const float*)d_in[1];
    float* out = (float*)d_out;

    k_fused<<<NGATE + NZERO, 256>>>(x, w, out);
    k_scan_scatter<<<B, 512>>>(out);
}